// round 9
// baseline (speedup 1.0000x reference)
#include <cuda_runtime.h>
#include <math.h>
#include <stdint.h>

// Problem constants
#define BB   8
#define SS   1024
#define HH   512
#define NHH  8
#define HDD  64

// Scratch for q, k, v in [B, NH, S, HD] layout (16 MB each).
__device__ float g_q[BB * NHH * SS * HDD];
__device__ float g_k[BB * NHH * SS * HDD];
__device__ float g_v[BB * NHH * SS * HDD];

// ---------------------------------------------------------------------------
// tf32 / mma / ldmatrix helpers
// ---------------------------------------------------------------------------
__device__ __forceinline__ unsigned f2tf(float x) {
    unsigned r;
    asm("cvt.rna.tf32.f32 %0, %1;" : "=r"(r) : "f"(x));
    return r;
}

// D(16x8,f32) += A(16x8,tf32,row) * B(8x8,tf32,col)
__device__ __forceinline__ void mma_tf32(float* d, const unsigned* a,
                                         const unsigned* b) {
    asm volatile(
        "mma.sync.aligned.m16n8k8.row.col.f32.tf32.tf32.f32 "
        "{%0,%1,%2,%3}, {%4,%5,%6,%7}, {%8,%9}, {%0,%1,%2,%3};"
        : "+f"(d[0]), "+f"(d[1]), "+f"(d[2]), "+f"(d[3])
        : "r"(a[0]), "r"(a[1]), "r"(a[2]), "r"(a[3]), "r"(b[0]), "r"(b[1]));
}

__device__ __forceinline__ void ldsm_x4(unsigned& r0, unsigned& r1,
                                        unsigned& r2, unsigned& r3,
                                        uint32_t addr) {
    asm volatile(
        "ldmatrix.sync.aligned.m8n8.x4.shared.b16 {%0,%1,%2,%3}, [%4];"
        : "=r"(r0), "=r"(r1), "=r"(r2), "=r"(r3) : "r"(addr));
}

__device__ __forceinline__ uint4 tf4(float4 t) {
    uint4 w;
    w.x = f2tf(t.x); w.y = f2tf(t.y); w.z = f2tf(t.z); w.w = f2tf(t.w);
    return w;
}

// ---------------------------------------------------------------------------
// Kernel 1: QKV projection, tf32 mma + ldmatrix + register-pipelined loads.
// CTA tile 128x128, BK=32. 8 warps: warp tile 64(m) x 32(n).
// grid = (4, 64, 3), block = 256.
// ---------------------------------------------------------------------------
#define QP 36   // smem pitch (words); 36 mod 8 = 4 -> ldmatrix conflict-free

__global__ __launch_bounds__(256, 1) void qkv_mma_kernel(
    const float* __restrict__ x,
    const float* __restrict__ Wq, const float* __restrict__ bq,
    const float* __restrict__ Wk, const float* __restrict__ bk,
    const float* __restrict__ Wv, const float* __restrict__ bv)
{
    __shared__ unsigned Xs[128][QP];
    __shared__ unsigned Ws[128][QP];

    const int z = blockIdx.z;
    const float* W    = (z == 0) ? Wq : (z == 1) ? Wk : Wv;
    const float* bias = (z == 0) ? bq : (z == 1) ? bk : bv;
    float*       out  = (z == 0) ? g_q : (z == 1) ? g_k : g_v;
    const float qscale = (z == 0) ? 0.125f : 1.0f;

    const int m0 = blockIdx.y * 128;
    const int n0 = blockIdx.x * 128;
    const int tid  = threadIdx.x;
    const int lane = tid & 31;
    const int wid  = tid >> 5;
    const int g    = lane >> 2;
    const int tig  = lane & 3;
    const int wm   = wid & 1;
    const int wn   = wid >> 1;

    const int lrow = tid >> 3;
    const int lcol = (tid & 7) * 4;

    const uint32_t xs_b = (uint32_t)__cvta_generic_to_shared(&Xs[0][0]);
    const uint32_t ws_b = (uint32_t)__cvta_generic_to_shared(&Ws[0][0]);
    uint32_t a_base[4];
#pragma unroll
    for (int mt = 0; mt < 4; mt++)
        a_base[mt] = xs_b + (uint32_t)((64 * wm + 16 * mt + (lane & 15)) * QP) * 4
                          + (uint32_t)(lane >> 4) * 16;
    uint32_t b_base[2];
#pragma unroll
    for (int p = 0; p < 2; p++)
        b_base[p] = ws_b + (uint32_t)((32 * wn + 16 * p + (lane & 7)
                          + (lane >> 4) * 8) * QP) * 4
                          + (uint32_t)((lane >> 3) & 1) * 16;

    float acc[4][4][4];
#pragma unroll
    for (int mt = 0; mt < 4; mt++)
#pragma unroll
        for (int nt = 0; nt < 4; nt++)
#pragma unroll
            for (int r = 0; r < 4; r++) acc[mt][nt][r] = 0.0f;

    // Prefetch chunk 0
    float4 xv[4], wv[4];
#pragma unroll
    for (int u = 0; u < 4; u++) {
        xv[u] = *reinterpret_cast<const float4*>(
            x + (size_t)(m0 + lrow + 32 * u) * HH + lcol);
        wv[u] = *reinterpret_cast<const float4*>(
            W + (size_t)(n0 + lrow + 32 * u) * HH + lcol);
    }

    for (int k0 = 0; k0 < HH; k0 += 32) {
        __syncthreads();   // previous chunk's ldmatrix readers are done
#pragma unroll
        for (int u = 0; u < 4; u++) {
            *reinterpret_cast<uint4*>(&Xs[lrow + 32 * u][lcol]) = tf4(xv[u]);
            *reinterpret_cast<uint4*>(&Ws[lrow + 32 * u][lcol]) = tf4(wv[u]);
        }
        // Prefetch next chunk: hides under this chunk's mma phase
        if (k0 + 32 < HH) {
#pragma unroll
            for (int u = 0; u < 4; u++) {
                xv[u] = *reinterpret_cast<const float4*>(
                    x + (size_t)(m0 + lrow + 32 * u) * HH + k0 + 32 + lcol);
                wv[u] = *reinterpret_cast<const float4*>(
                    W + (size_t)(n0 + lrow + 32 * u) * HH + k0 + 32 + lcol);
            }
        }
        __syncthreads();

#pragma unroll
        for (int kc = 0; kc < 4; kc++) {
            const uint32_t koff = (uint32_t)kc * 32;
            unsigned af[4][4];
#pragma unroll
            for (int mt = 0; mt < 4; mt++)
                ldsm_x4(af[mt][0], af[mt][1], af[mt][2], af[mt][3],
                        a_base[mt] + koff);
            unsigned bf[2][4];
#pragma unroll
            for (int p = 0; p < 2; p++)
                ldsm_x4(bf[p][0], bf[p][1], bf[p][2], bf[p][3],
                        b_base[p] + koff);
#pragma unroll
            for (int mt = 0; mt < 4; mt++)
#pragma unroll
                for (int p = 0; p < 2; p++) {
                    mma_tf32(acc[mt][2 * p],     af[mt], &bf[p][0]);
                    mma_tf32(acc[mt][2 * p + 1], af[mt], &bf[p][2]);
                }
        }
    }

    // Epilogue: bias, q scale, scatter into [B, NH, S, HD]
#pragma unroll
    for (int mt = 0; mt < 4; mt++) {
        const int mrow0 = m0 + 64 * wm + 16 * mt + g;
#pragma unroll
        for (int nt = 0; nt < 4; nt++) {
            const int n = n0 + 32 * wn + 8 * nt + 2 * tig;
            const float2 bb = *reinterpret_cast<const float2*>(bias + n);
            const int head = n >> 6;
            const int d = n & 63;
#pragma unroll
            for (int hv = 0; hv < 2; hv++) {
                const int m = mrow0 + 8 * hv;
                const int b = m >> 10;
                const int s = m & 1023;
                float2 val;
                val.x = (acc[mt][nt][2 * hv]     + bb.x) * qscale;
                val.y = (acc[mt][nt][2 * hv + 1] + bb.y) * qscale;
                *reinterpret_cast<float2*>(
                    out + (((size_t)(b * NHH + head)) * SS + s) * HDD + d) = val;
            }
        }
    }
}

// ---------------------------------------------------------------------------
// Kernel 2: flash attention, tf32 mma + ldmatrix + register-pipelined K/V.
// CTA: 128 q-rows x one (b,h). 8 warps x 16 q-rows. 64-key tiles.
// grid = (8, NH, B), block = 256, 1 CTA/SM (regs), smem ~105 KB.
// ---------------------------------------------------------------------------
#define AP 68   // pitch (words) for q/k/p; 68 mod 8 = 4 -> ldmatrix clean
#define VP 72   // pitch for v; bank = 8*tig+8*nt+g bijective -> LDS clean

__global__ __launch_bounds__(256, 1) void attn_mma_kernel(
    const float* __restrict__ rel,    // [B, NH, S, S]
    const float* __restrict__ mask,   // [B, 1, 1, S]
    float* __restrict__ out)          // [B, S, H]
{
    extern __shared__ unsigned sm[];
    unsigned* q_s = sm;                      // [128][AP]
    unsigned* k_s = q_s + 128 * AP;          // [64][AP]
    unsigned* v_s = k_s + 64 * AP;           // [64][VP]
    unsigned* p_s = v_s + 64 * VP;           // [128][AP]

    const int b  = blockIdx.z;
    const int h  = blockIdx.y;
    const int q0 = blockIdx.x * 128;
    const int bh = b * NHH + h;

    const int tid  = threadIdx.x;
    const int lane = tid & 31;
    const int wid  = tid >> 5;     // 0..7
    const int g    = lane >> 2;
    const int tig  = lane & 3;
    const int qr   = 16 * wid;     // warp's q-row base in tile

    const float* qg = g_q + (size_t)bh * SS * HDD;
    const float* kg = g_k + (size_t)bh * SS * HDD;
    const float* vg = g_v + (size_t)bh * SS * HDD;

    const uint32_t q_sb = (uint32_t)__cvta_generic_to_shared(q_s);
    const uint32_t k_sb = (uint32_t)__cvta_generic_to_shared(k_s);
    const uint32_t p_sb = (uint32_t)__cvta_generic_to_shared(p_s);

    const uint32_t rofs = (uint32_t)((qr + (lane & 15)) * AP) * 4
                        + (uint32_t)(lane >> 4) * 16;
    const uint32_t qa_base = q_sb + rofs;
    const uint32_t pa_base = p_sb + rofs;
    uint32_t kb_base[4];
#pragma unroll
    for (int p = 0; p < 4; p++)
        kb_base[p] = k_sb + (uint32_t)((16 * p + (lane & 7)
                           + (lane >> 4) * 8) * AP) * 4
                           + (uint32_t)((lane >> 3) & 1) * 16;

    // Load Q tile (128x64), tf32-rounded: 8 float4 per thread
#pragma unroll
    for (int u = 0; u < 8; u++) {
        const int lin = tid + 256 * u;
        const int row = lin >> 4;
        const int c4  = (lin & 15) * 4;
        float4 t = *reinterpret_cast<const float4*>(
            qg + (size_t)(q0 + row) * HDD + c4);
        *reinterpret_cast<uint4*>(q_s + row * AP + c4) = tf4(t);
    }

    // Prefetch K/V tile 0 into registers (4 float4 each)
    const int pr_row = tid >> 4;           // 0..15 (+16u)
    const int pr_c4  = (tid & 15) * 4;
    float4 kt[4], vt[4];
#pragma unroll
    for (int u = 0; u < 4; u++) {
        kt[u] = *reinterpret_cast<const float4*>(
            kg + (size_t)(pr_row + 16 * u) * HDD + pr_c4);
        vt[u] = *reinterpret_cast<const float4*>(
            vg + (size_t)(pr_row + 16 * u) * HDD + pr_c4);
    }

    float m0v = -1e30f, m1v = -1e30f, l0v = 0.0f, l1v = 0.0f;
    float o[8][4];
#pragma unroll
    for (int nt = 0; nt < 8; nt++)
#pragma unroll
        for (int r = 0; r < 4; r++) o[nt][r] = 0.0f;

    for (int k0 = 0; k0 < SS; k0 += 64) {
        // Init score accumulators with rel + mask (LDGs issue here; consumed
        // after the score mma — latency hides under STS + sync + scores).
        float sc[8][4];
        {
            const size_t rb = ((size_t)bh * SS + (q0 + qr + g)) * SS
                            + k0 + 2 * tig;
#pragma unroll
            for (int nt = 0; nt < 8; nt++) {
                float2 mk = *reinterpret_cast<const float2*>(
                    mask + b * SS + k0 + 8 * nt + 2 * tig);
                float2 rA = *reinterpret_cast<const float2*>(rel + rb + 8 * nt);
                float2 rB = *reinterpret_cast<const float2*>(
                    rel + rb + 8 * (size_t)SS + 8 * nt);
                sc[nt][0] = rA.x + mk.x;
                sc[nt][1] = rA.y + mk.y;
                sc[nt][2] = rB.x + mk.x;
                sc[nt][3] = rB.y + mk.y;
            }
        }

        __syncthreads();   // previous tile's k_s/v_s readers are done

        // Store prefetched K/V (tf32) to smem
#pragma unroll
        for (int u = 0; u < 4; u++) {
            const int row = pr_row + 16 * u;
            *reinterpret_cast<uint4*>(k_s + row * AP + pr_c4) = tf4(kt[u]);
            *reinterpret_cast<uint4*>(v_s + row * VP + pr_c4) = tf4(vt[u]);
        }

        // Prefetch next tile's K/V: hides under the whole compute phase below
        if (k0 + 64 < SS) {
#pragma unroll
            for (int u = 0; u < 4; u++) {
                kt[u] = *reinterpret_cast<const float4*>(
                    kg + (size_t)(k0 + 64 + pr_row + 16 * u) * HDD + pr_c4);
                vt[u] = *reinterpret_cast<const float4*>(
                    vg + (size_t)(k0 + 64 + pr_row + 16 * u) * HDD + pr_c4);
            }
        }
        __syncthreads();

        // Scores: S(16x64) += Q_w (16x64) * K^T
#pragma unroll
        for (int kc = 0; kc < 8; kc++) {
            const uint32_t koff = (uint32_t)kc * 32;
            unsigned af[4];
            ldsm_x4(af[0], af[1], af[2], af[3], qa_base + koff);
#pragma unroll
            for (int p = 0; p < 4; p++) {
                unsigned bf[4];
                ldsm_x4(bf[0], bf[1], bf[2], bf[3], kb_base[p] + koff);
                mma_tf32(sc[2 * p],     af, &bf[0]);
                mma_tf32(sc[2 * p + 1], af, &bf[2]);
            }
        }

        // Online softmax (rows qr+g, qr+g+8; quad reduce via shfl)
        {
            float tm0 = sc[0][0], tm1 = sc[0][2];
#pragma unroll
            for (int nt = 0; nt < 8; nt++) {
                tm0 = fmaxf(tm0, fmaxf(sc[nt][0], sc[nt][1]));
                tm1 = fmaxf(tm1, fmaxf(sc[nt][2], sc[nt][3]));
            }
            tm0 = fmaxf(tm0, __shfl_xor_sync(0xffffffffu, tm0, 1));
            tm0 = fmaxf(tm0, __shfl_xor_sync(0xffffffffu, tm0, 2));
            tm1 = fmaxf(tm1, __shfl_xor_sync(0xffffffffu, tm1, 1));
            tm1 = fmaxf(tm1, __shfl_xor_sync(0xffffffffu, tm1, 2));

            const float mn0 = fmaxf(m0v, tm0);
            const float mn1 = fmaxf(m1v, tm1);
            const float c0 = __expf(m0v - mn0);
            const float c1 = __expf(m1v - mn1);
            float ls0 = 0.0f, ls1 = 0.0f;
#pragma unroll
            for (int nt = 0; nt < 8; nt++) {
                sc[nt][0] = __expf(sc[nt][0] - mn0);
                sc[nt][1] = __expf(sc[nt][1] - mn0);
                sc[nt][2] = __expf(sc[nt][2] - mn1);
                sc[nt][3] = __expf(sc[nt][3] - mn1);
                ls0 += sc[nt][0] + sc[nt][1];
                ls1 += sc[nt][2] + sc[nt][3];
            }
            ls0 += __shfl_xor_sync(0xffffffffu, ls0, 1);
            ls0 += __shfl_xor_sync(0xffffffffu, ls0, 2);
            ls1 += __shfl_xor_sync(0xffffffffu, ls1, 1);
            ls1 += __shfl_xor_sync(0xffffffffu, ls1, 2);

            l0v = l0v * c0 + ls0;
            l1v = l1v * c1 + ls1;
            m0v = mn0; m1v = mn1;
#pragma unroll
            for (int nt = 0; nt < 8; nt++) {
                o[nt][0] *= c0; o[nt][1] *= c0;
                o[nt][2] *= c1; o[nt][3] *= c1;
            }
        }

        // C-frag -> A-frag via per-warp p_s slice (warp-local)
        __syncwarp();
        {
            const int r0w = qr + g;
#pragma unroll
            for (int nt = 0; nt < 8; nt++) {
                const int col = 8 * nt + 2 * tig;
                uint2 lo, hi;
                lo.x = f2tf(sc[nt][0]); lo.y = f2tf(sc[nt][1]);
                hi.x = f2tf(sc[nt][2]); hi.y = f2tf(sc[nt][3]);
                *reinterpret_cast<uint2*>(p_s + r0w * AP + col) = lo;
                *reinterpret_cast<uint2*>(p_s + (r0w + 8) * AP + col) = hi;
            }
        }
        __syncwarp();

        // O(16x64) += P(16x64) * V(64x64)
#pragma unroll
        for (int kc = 0; kc < 8; kc++) {
            const uint32_t koff = (uint32_t)kc * 32;
            unsigned af[4];
            ldsm_x4(af[0], af[1], af[2], af[3], pa_base + koff);
#pragma unroll
            for (int nt = 0; nt < 8; nt++) {
                unsigned bf[2];
                bf[0] = v_s[(8 * kc + tig) * VP + 8 * nt + g];
                bf[1] = v_s[(8 * kc + tig + 4) * VP + 8 * nt + g];
                mma_tf32(o[nt], af, bf);
            }
        }
    }

    // Epilogue: normalize, write ctx to [B, S, H]
    const float inv0 = 1.0f / l0v;
    const float inv1 = 1.0f / l1v;
    const int s0 = q0 + qr + g;
    float* orow0 = out + ((size_t)(b * SS + s0)) * HH + h * HDD;
    float* orow1 = out + ((size_t)(b * SS + s0 + 8)) * HH + h * HDD;
#pragma unroll
    for (int nt = 0; nt < 8; nt++) {
        const int col = 8 * nt + 2 * tig;
        float2 v0, v1;
        v0.x = o[nt][0] * inv0; v0.y = o[nt][1] * inv0;
        v1.x = o[nt][2] * inv1; v1.y = o[nt][3] * inv1;
        *reinterpret_cast<float2*>(orow0 + col) = v0;
        *reinterpret_cast<float2*>(orow1 + col) = v1;
    }
}

// ---------------------------------------------------------------------------
// Launch
// ---------------------------------------------------------------------------
extern "C" void kernel_launch(void* const* d_in, const int* in_sizes, int n_in,
                              void* d_out, int out_size)
{
    const float* hidden = (const float*)d_in[0];
    const float* mask   = (const float*)d_in[1];
    const float* rel    = (const float*)d_in[2];
    const float* Wq     = (const float*)d_in[3];
    const float* bq     = (const float*)d_in[4];
    const float* Wk     = (const float*)d_in[5];
    const float* bk     = (const float*)d_in[6];
    const float* Wv     = (const float*)d_in[7];
    const float* bv     = (const float*)d_in[8];
    float* out = (float*)d_out;

    const int attn_smem =
        (128 * AP + 64 * AP + 64 * VP + 128 * AP) * (int)sizeof(unsigned);
    cudaFuncSetAttribute(attn_mma_kernel,
                         cudaFuncAttributeMaxDynamicSharedMemorySize,
                         attn_smem);

    // QKV projection: grid (N/128, M/128, 3)
    qkv_mma_kernel<<<dim3(HH / 128, (BB * SS) / 128, 3), 256>>>(
        hidden, Wq, bq, Wk, bk, Wv, bv);

    // Attention: grid (S/128, NH, B)
    attn_mma_kernel<<<dim3(SS / 128, NHH, BB), 256, attn_smem>>>(
        rel, mask, out);
}